// round 1
// baseline (speedup 1.0000x reference)
#include <cuda_runtime.h>
#include <math.h>

#define BB 1536
#define NG 64
#define NP 24
#define ED 64
#define HD 128
#define SEQ 12

// ---------------- scratch (static device globals; no allocation) -------------
__device__ float g_h[BB*HD];        // carry hidden (refreshed by mlp2)
__device__ float g_c[BB*HD];        // LSTM cell
__device__ float g_hl[BB*HD];       // LSTM output h for this step
__device__ float g_lp[BB*2];        // current position (last_pos, updated)
__device__ float g_decin[BB*ED];    // decoder input embedding
__device__ float g_hcon[BB*512];    // h @ Wp1_h^T + combined bias (pre-relu)
__device__ float g_pool[BB*1024];   // pooled features
__device__ float g_mh[BB*1024];     // mlp hidden
__device__ float g_M[512*2];        // Wp1_e @ Wp_emb  (512x2)
__device__ float g_biasc[512];      // bp1 + Wp1_e @ bp_emb
__device__ float g_WihT[64*512];    // transposed LSTM weights
__device__ float g_WhhT[128*512];

// ---------------- precompute: transpose LSTM weights, fold pool layer-1 ------
__global__ void precompute_kernel(const float* __restrict__ Wih,
                                  const float* __restrict__ Whh,
                                  const float* __restrict__ Wp1,
                                  const float* __restrict__ Wp_emb,
                                  const float* __restrict__ bp_emb,
                                  const float* __restrict__ bp1) {
    int idx = blockIdx.x * blockDim.x + threadIdx.x;
    if (idx < 512*64)  { int r = idx/64,  c = idx%64;  g_WihT[c*512 + r] = Wih[idx]; }
    if (idx < 512*128) { int r = idx/128, c = idx%128; g_WhhT[c*512 + r] = Whh[idx]; }
    if (idx < 512) {
        float m0 = 0.f, m1 = 0.f, bc = 0.f;
        for (int e = 0; e < 64; e++) {
            float w = Wp1[idx*192 + e];
            m0 += w * Wp_emb[e*2 + 0];
            m1 += w * Wp_emb[e*2 + 1];
            bc += w * bp_emb[e];
        }
        g_M[idx*2 + 0] = m0;
        g_M[idx*2 + 1] = m1;
        g_biasc[idx] = bp1[idx] + bc;
    }
}

// ---------------- init: carry state + first decoder input --------------------
__global__ void init_kernel(const float* __restrict__ h0, const float* __restrict__ c0,
                            const float* __restrict__ lp, const float* __restrict__ lpr,
                            const float* __restrict__ Wemb, const float* __restrict__ bemb) {
    int idx = blockIdx.x * blockDim.x + threadIdx.x;
    if (idx < BB*HD) { g_h[idx] = h0[idx]; g_c[idx] = c0[idx]; }
    if (idx < BB*2)  { g_lp[idx] = lp[idx]; }
    if (idx < BB*ED) {
        int b = idx / ED, e = idx % ED;
        g_decin[idx] = lpr[b*2]*Wemb[e*2] + lpr[b*2+1]*Wemb[e*2+1] + bemb[e];
    }
}

// ---------------- fused LSTM step: gates + activations -----------------------
// 256 threads: unit u = tid&127, half rh = tid>>7; block handles 8 batch rows.
__global__ void lstm_kernel(const float* __restrict__ bih, const float* __restrict__ bhh) {
    int tid = threadIdx.x;
    int u = tid & 127;
    int rh = tid >> 7;           // 0 or 1 -> rows rh*4 .. rh*4+3
    int r0 = blockIdx.x * 8;
    __shared__ float xs[8][64];
    __shared__ float hs[8][128];
    for (int l = tid; l < 8*64;  l += 256) xs[l>>6][l&63]   = g_decin[r0*64  + l];
    for (int l = tid; l < 8*128; l += 256) hs[l>>7][l&127]  = g_h[r0*128 + l];
    __syncthreads();

    float acc[4][4];
    #pragma unroll
    for (int gt = 0; gt < 4; gt++) {
        float bb = bih[u + gt*128] + bhh[u + gt*128];
        #pragma unroll
        for (int r = 0; r < 4; r++) acc[gt][r] = bb;
    }
    for (int e = 0; e < 64; e++) {
        float w0 = g_WihT[e*512 + u];
        float w1 = g_WihT[e*512 + u + 128];
        float w2 = g_WihT[e*512 + u + 256];
        float w3 = g_WihT[e*512 + u + 384];
        #pragma unroll
        for (int r = 0; r < 4; r++) {
            float x = xs[rh*4 + r][e];
            acc[0][r] += w0*x; acc[1][r] += w1*x; acc[2][r] += w2*x; acc[3][r] += w3*x;
        }
    }
    for (int e = 0; e < 128; e++) {
        float w0 = g_WhhT[e*512 + u];
        float w1 = g_WhhT[e*512 + u + 128];
        float w2 = g_WhhT[e*512 + u + 256];
        float w3 = g_WhhT[e*512 + u + 384];
        #pragma unroll
        for (int r = 0; r < 4; r++) {
            float x = hs[rh*4 + r][e];
            acc[0][r] += w0*x; acc[1][r] += w1*x; acc[2][r] += w2*x; acc[3][r] += w3*x;
        }
    }
    #pragma unroll
    for (int r = 0; r < 4; r++) {
        int row = r0 + rh*4 + r;
        float ig = 1.f / (1.f + __expf(-acc[0][r]));
        float fg = 1.f / (1.f + __expf(-acc[1][r]));
        float gg = tanhf(acc[2][r]);
        float og = 1.f / (1.f + __expf(-acc[3][r]));
        int bi = row*128 + u;
        float cc = fg * g_c[bi] + ig * gg;
        g_c[bi]  = cc;
        g_hl[bi] = og * tanhf(cc);
    }
}

// ---------------- rel_pos, position update, rels output, next dec_in ---------
__global__ void posdec_kernel(const float* __restrict__ Wpos, const float* __restrict__ bpos,
                              const float* __restrict__ Wemb, const float* __restrict__ bemb,
                              float* __restrict__ rels_out, int step) {
    int b = blockIdx.x;
    int t = threadIdx.x;
    __shared__ float hr[128];
    __shared__ float sr[2];
    hr[t] = g_hl[b*128 + t];
    __syncthreads();
    int w = t >> 5, lane = t & 31;
    if (w < 2) {
        float part = 0.f;
        for (int k = lane; k < 128; k += 32) part += hr[k] * Wpos[w*128 + k];
        #pragma unroll
        for (int off = 16; off; off >>= 1) part += __shfl_down_sync(0xffffffffu, part, off);
        if (lane == 0) sr[w] = part + bpos[w];
    }
    __syncthreads();
    float ra = sr[0], rb = sr[1];
    if (t < 64) g_decin[b*64 + t] = ra*Wemb[t*2] + rb*Wemb[t*2+1] + bemb[t];
    if (t == 0) {
        rels_out[(step*BB + b)*2 + 0] = ra;
        rels_out[(step*BB + b)*2 + 1] = rb;
        g_lp[b*2 + 0] += ra;
        g_lp[b*2 + 1] += rb;
    }
}

// ---------------- generic tiled SGEMM: C = act(Aconcat @ B^T + bias) ---------
// BM=BN=64, BK=16, 256 threads, 4x4 per thread (strided frags).
__global__ void gemm_kernel(const float* __restrict__ A1, int lda1,
                            const float* __restrict__ A2, int lda2, int split,
                            const float* __restrict__ Bm, int ldb,
                            const float* __restrict__ bias,
                            float* __restrict__ Cm, int ldc,
                            int Kdim, int doRelu) {
    __shared__ float As[16][69];
    __shared__ float Bs[16][69];
    int tid = threadIdx.x;
    int tx = tid & 15, ty = tid >> 4;
    int n0 = blockIdx.x * 64, m0 = blockIdx.y * 64;
    float acc[4][4] = {};
    for (int k0 = 0; k0 < Kdim; k0 += 16) {
        for (int l = tid; l < 1024; l += 256) {
            int mm = l >> 4, kk = l & 15;
            int kg = k0 + kk;
            float v = (kg < split) ? A1[(m0+mm)*lda1 + kg]
                                   : A2[(m0+mm)*lda2 + (kg - split)];
            As[kk][mm] = v;
        }
        for (int l = tid; l < 1024; l += 256) {
            int nn = l >> 4, kk = l & 15;
            Bs[kk][nn] = Bm[(n0+nn)*ldb + k0 + kk];
        }
        __syncthreads();
        #pragma unroll
        for (int kk = 0; kk < 16; kk++) {
            float a[4], bv[4];
            #pragma unroll
            for (int i = 0; i < 4; i++) a[i]  = As[kk][ty + 16*i];
            #pragma unroll
            for (int j = 0; j < 4; j++) bv[j] = Bs[kk][tx + 16*j];
            #pragma unroll
            for (int i = 0; i < 4; i++)
                #pragma unroll
                for (int j = 0; j < 4; j++)
                    acc[i][j] += a[i] * bv[j];
        }
        __syncthreads();
    }
    #pragma unroll
    for (int i = 0; i < 4; i++) {
        int m = m0 + ty + 16*i;
        #pragma unroll
        for (int j = 0; j < 4; j++) {
            int n = n0 + tx + 16*j;
            float v = acc[i][j] + bias[n];
            if (doRelu) v = fmaxf(v, 0.f);
            Cm[m*ldc + n] = v;
        }
    }
}

// ---------------- pool kernel: fused layer1 + layer2 GEMM + max over j -------
// Block tile: 4 i's x 24 j's = 96 rows, 128 output cols, K=512 in BK=32 tiles.
// A[r,k] = relu(ra[r]*M[k,0] + rb[r]*M[k,1] + hcon[g*24+j(r), k]) built in smem.
__global__ void pool_kernel(const float* __restrict__ Wp2, const float* __restrict__ bp2) {
    int g  = blockIdx.z;
    int i0 = blockIdx.y * 4;
    int n0 = blockIdx.x * 128;
    __shared__ float As[32][101];   // [k][row]
    __shared__ float Bs[32][133];   // [k][n]
    __shared__ float ra[96], rb[96];
    __shared__ int   red[4][128];
    int tid = threadIdx.x;
    int tx = tid & 15, ty = tid >> 4;

    if (tid < 96) {
        int il = tid / 24, j = tid % 24;
        float pix = g_lp[(g*24 + i0 + il)*2 + 0];
        float piy = g_lp[(g*24 + i0 + il)*2 + 1];
        float pjx = g_lp[(g*24 + j)*2 + 0];
        float pjy = g_lp[(g*24 + j)*2 + 1];
        float dx = pjx - pix, dy = pjy - piy;
        float nrm = sqrtf(dx*dx + dy*dy);
        float inv = 1.f / fmaxf(nrm, 1e-12f);
        ra[tid] = dx * inv;
        rb[tid] = dy * inv;
    }
    for (int l = tid; l < 512; l += 256) red[l >> 7][l & 127] = 0;
    __syncthreads();

    float acc[6][8] = {};
    for (int k0 = 0; k0 < 512; k0 += 32) {
        // A tile: 96x32, fused layer-1
        for (int l = tid; l < 3072; l += 256) {
            int r = l >> 5, kk = l & 31;
            int j = r % 24;
            int kg = k0 + kk;
            float hc = g_hcon[(g*24 + j)*512 + kg];
            float v = ra[r]*g_M[kg*2] + rb[r]*g_M[kg*2 + 1] + hc;
            As[kk][r] = fmaxf(v, 0.f);
        }
        // B tile: 128x32 of Wp2
        for (int l = tid; l < 4096; l += 256) {
            int n = l >> 5, kk = l & 31;
            Bs[kk][n] = Wp2[(n0 + n)*512 + k0 + kk];
        }
        __syncthreads();
        #pragma unroll
        for (int kk = 0; kk < 32; kk++) {
            float a[6], bv[8];
            #pragma unroll
            for (int i = 0; i < 6; i++) a[i]  = As[kk][ty + 16*i];
            #pragma unroll
            for (int j = 0; j < 8; j++) bv[j] = Bs[kk][tx + 16*j];
            #pragma unroll
            for (int i = 0; i < 6; i++)
                #pragma unroll
                for (int j = 0; j < 8; j++)
                    acc[i][j] += a[i] * bv[j];
        }
        __syncthreads();
    }
    // epilogue: relu(+bias) then max over the 24 j-rows of each i group.
    // relu output >= 0, so int atomicMax on float bits is order-preserving.
    #pragma unroll
    for (int i = 0; i < 6; i++) {
        int r = ty + 16*i;
        int il = r / 24;
        #pragma unroll
        for (int j = 0; j < 8; j++) {
            int n = tx + 16*j;
            float z = fmaxf(acc[i][j] + bp2[n0 + n], 0.f);
            atomicMax(&red[il][n], __float_as_int(z));
        }
    }
    __syncthreads();
    for (int l = tid; l < 512; l += 256) {
        int il = l >> 7, n = l & 127;
        g_pool[(g*24 + i0 + il)*1024 + n0 + n] = __int_as_float(red[il][n]);
    }
}

// ---------------- final hidden copy ------------------------------------------
__global__ void copyout_kernel(float* __restrict__ out) {
    int idx = blockIdx.x * blockDim.x + threadIdx.x;
    if (idx < BB*HD) out[SEQ*BB*2 + idx] = g_h[idx];
}

// ---------------- launch ------------------------------------------------------
static float* sym_addr(const void* sym) {
    void* p = nullptr;
    cudaGetSymbolAddress(&p, sym);
    return (float*)p;
}

extern "C" void kernel_launch(void* const* d_in, const int* in_sizes, int n_in,
                              void* d_out, int out_size) {
    const float* last_pos     = (const float*)d_in[0];
    const float* last_pos_rel = (const float*)d_in[1];
    const float* h0    = (const float*)d_in[2];
    const float* c0    = (const float*)d_in[3];
    // d_in[4] seq_start_end: groups are contiguous/equal-size -> unused
    const float* W_emb = (const float*)d_in[5];
    const float* b_emb = (const float*)d_in[6];
    const float* W_ih  = (const float*)d_in[7];
    const float* W_hh  = (const float*)d_in[8];
    const float* b_ih  = (const float*)d_in[9];
    const float* b_hh  = (const float*)d_in[10];
    const float* W_pos = (const float*)d_in[11];
    const float* b_pos = (const float*)d_in[12];
    const float* Wp_emb= (const float*)d_in[13];
    const float* bp_emb= (const float*)d_in[14];
    const float* Wp1   = (const float*)d_in[15];
    const float* bp1   = (const float*)d_in[16];
    const float* Wp2   = (const float*)d_in[17];
    const float* bp2   = (const float*)d_in[18];
    const float* Wm1   = (const float*)d_in[19];
    const float* bm1   = (const float*)d_in[20];
    const float* Wm2   = (const float*)d_in[21];
    const float* bm2   = (const float*)d_in[22];
    float* out = (float*)d_out;

    float* p_hl    = sym_addr(g_hl);
    float* p_h     = sym_addr(g_h);
    float* p_hcon  = sym_addr(g_hcon);
    float* p_pool  = sym_addr(g_pool);
    float* p_mh    = sym_addr(g_mh);
    float* p_biasc = sym_addr(g_biasc);

    precompute_kernel<<<(512*128 + 255)/256, 256>>>(W_ih, W_hh, Wp1, Wp_emb, bp_emb, bp1);
    init_kernel<<<(BB*HD + 255)/256, 256>>>(h0, c0, last_pos, last_pos_rel, W_emb, b_emb);

    for (int s = 0; s < SEQ; s++) {
        lstm_kernel<<<BB/8, 256>>>(b_ih, b_hh);
        posdec_kernel<<<BB, 128>>>(W_pos, b_pos, W_emb, b_emb, out, s);
        // hcon = hl @ Wp1_h^T + (bp1 + Wp1_e@bp_emb):  [1536,512], K=128
        gemm_kernel<<<dim3(512/64, BB/64), 256>>>(
            p_hl, 128, p_hl, 128, 1 << 28,
            Wp1 + 64, 192, p_biasc, p_hcon, 512, 128, 0);
        // pool: fused layer1 + [36864,512]@[512,1024]^T + max over j
        pool_kernel<<<dim3(8, 6, NG), 256>>>(Wp2, bp2);
        // mlp1: concat(hl, pool) [1536,1152] @ Wm1^T -> [1536,1024], relu
        gemm_kernel<<<dim3(1024/64, BB/64), 256>>>(
            p_hl, 128, p_pool, 1024, 128,
            Wm1, 1152, bm1, p_mh, 1024, 1152, 1);
        // mlp2: [1536,1024] @ Wm2^T -> [1536,128], relu -> refreshed h (carry)
        gemm_kernel<<<dim3(128/64, BB/64), 256>>>(
            p_mh, 1024, p_mh, 1024, 1 << 28,
            Wm2, 1024, bm2, p_h, 128, 1024, 1);
    }
    copyout_kernel<<<(BB*HD + 255)/256, 256>>>(out);
}